// round 16
// baseline (speedup 1.0000x reference)
#include <cuda_runtime.h>
#include <cuda_bf16.h>
#include <cstdint>

typedef unsigned long long ull;

// ---------------- problem constants ----------------
#define BSZ 2
#define SEQ 2048
#define HID 2048
#define HD  256
#define NH  8
#define SCALING 0.0625f

// ---------------- scratch (device globals) ----------------
__device__ float g_Qp [(long)BSZ*SEQ*NH*HD];
__device__ float g_Q  [(long)BSZ*NH*SEQ*HD];
__device__ float g_KV [(long)BSZ*SEQ*512];
__device__ float g_Kt [(long)BSZ*HD*SEQ];
__device__ float g_AO [(long)BSZ*SEQ*NH*HD];
__device__ float g_Wkv[(long)HID*512];

// ---------------- f32x2 helpers ----------------
__device__ __forceinline__ ull pk2(float x) {
    ull r; unsigned u = __float_as_uint(x);
    asm("mov.b64 %0, {%1, %1};" : "=l"(r) : "r"(u));
    return r;
}
__device__ __forceinline__ ull fma2(ull a, ull b, ull c) {
    ull d;
    asm("fma.rn.f32x2 %0, %1, %2, %3;" : "=l"(d) : "l"(a), "l"(b), "l"(c));
    return d;
}
__device__ __forceinline__ float2 unpk2(ull v) {
    unsigned lo, hi;
    asm("mov.b64 {%0, %1}, %2;" : "=r"(lo), "=r"(hi) : "l"(v));
    return make_float2(__uint_as_float(lo), __uint_as_float(hi));
}

#define BKC 16
#define A_BUF 4096
#define B_BUF 2048
#define SMEM_DYN ((2*A_BUF + 2*B_BUF) * 4)   // 48 KB

// inner 16-k fma block (shared by both GEMMs)
#define FMA_BLOCK(sa, sb)                                                      \
    _Pragma("unroll")                                                          \
    for (int k = 0; k < BKC; k++) {                                            \
        ulonglong2 aa0 = *(const ulonglong2*)&(sa)[k * 256 + mbase];           \
        ulonglong2 aa1 = *(const ulonglong2*)&(sa)[k * 256 + mbase + 4];       \
        ulonglong2 aa2 = *(const ulonglong2*)&(sa)[k * 256 + mbase + 8];       \
        ulonglong2 aa3 = *(const ulonglong2*)&(sa)[k * 256 + mbase + 12];      \
        float4 bv = *(const float4*)&(sb)[k * 128 + nbase];                    \
        const ull b0 = pk2(bv.x), b1 = pk2(bv.y), b2 = pk2(bv.z), b3 = pk2(bv.w); \
        acc[0][0] = fma2(aa0.x, b0, acc[0][0]);                                \
        acc[0][1] = fma2(aa0.x, b1, acc[0][1]);                                \
        acc[0][2] = fma2(aa0.x, b2, acc[0][2]);                                \
        acc[0][3] = fma2(aa0.x, b3, acc[0][3]);                                \
        acc[1][0] = fma2(aa0.y, b0, acc[1][0]);                                \
        acc[1][1] = fma2(aa0.y, b1, acc[1][1]);                                \
        acc[1][2] = fma2(aa0.y, b2, acc[1][2]);                                \
        acc[1][3] = fma2(aa0.y, b3, acc[1][3]);                                \
        acc[2][0] = fma2(aa1.x, b0, acc[2][0]);                                \
        acc[2][1] = fma2(aa1.x, b1, acc[2][1]);                                \
        acc[2][2] = fma2(aa1.x, b2, acc[2][2]);                                \
        acc[2][3] = fma2(aa1.x, b3, acc[2][3]);                                \
        acc[3][0] = fma2(aa1.y, b0, acc[3][0]);                                \
        acc[3][1] = fma2(aa1.y, b1, acc[3][1]);                                \
        acc[3][2] = fma2(aa1.y, b2, acc[3][2]);                                \
        acc[3][3] = fma2(aa1.y, b3, acc[3][3]);                                \
        acc[4][0] = fma2(aa2.x, b0, acc[4][0]);                                \
        acc[4][1] = fma2(aa2.x, b1, acc[4][1]);                                \
        acc[4][2] = fma2(aa2.x, b2, acc[4][2]);                                \
        acc[4][3] = fma2(aa2.x, b3, acc[4][3]);                                \
        acc[5][0] = fma2(aa2.y, b0, acc[5][0]);                                \
        acc[5][1] = fma2(aa2.y, b1, acc[5][1]);                                \
        acc[5][2] = fma2(aa2.y, b2, acc[5][2]);                                \
        acc[5][3] = fma2(aa2.y, b3, acc[5][3]);                                \
        acc[6][0] = fma2(aa3.x, b0, acc[6][0]);                                \
        acc[6][1] = fma2(aa3.x, b1, acc[6][1]);                                \
        acc[6][2] = fma2(aa3.x, b2, acc[6][2]);                                \
        acc[6][3] = fma2(aa3.x, b3, acc[6][3]);                                \
        acc[7][0] = fma2(aa3.y, b0, acc[7][0]);                                \
        acc[7][1] = fma2(aa3.y, b1, acc[7][1]);                                \
        acc[7][2] = fma2(aa3.y, b2, acc[7][2]);                                \
        acc[7][3] = fma2(aa3.y, b3, acc[7][3]);                                \
    }

#define STORE_A_STAGE(dst)                                                     \
    (dst)[(ac + 0) * 256 + ar] = pa0.x; (dst)[(ac + 1) * 256 + ar] = pa0.y;    \
    (dst)[(ac + 2) * 256 + ar] = pa0.z; (dst)[(ac + 3) * 256 + ar] = pa0.w;    \
    (dst)[(ac + 4) * 256 + ar] = pa1.x; (dst)[(ac + 5) * 256 + ar] = pa1.y;    \
    (dst)[(ac + 6) * 256 + ar] = pa1.z; (dst)[(ac + 7) * 256 + ar] = pa1.w;

// ============ sgemm4: 256x128 tile, 512 threads, dynamic K ============
__global__ __launch_bounds__(512)
void sgemm4(const float* __restrict__ A, const float* __restrict__ B,
            float* __restrict__ C,
            int K, int lda, int ldb, int ldc,
            long sAz, long sBb, long sCb, long sCh, int nh,
            int causalPV)
{
    extern __shared__ float sm[];
    const int tid = threadIdx.x;
    const int z = blockIdx.z, b = z / nh, h = z - b * nh;
    int rowT = blockIdx.y;
    if (causalPV) rowT = gridDim.y - 1 - rowT;
    const int colT = blockIdx.x;

    A += (long)z * sAz + (long)(rowT * 256) * lda;
    B += (long)b * sBb + colT * 128;
    C += (long)b * sCb + (long)h * sCh;

    const int Keff = causalPV ? min(K, (rowT + 1) * 256) : K;
    const int nk = Keff >> 4;

    const int w    = tid >> 5;
    const int lane = tid & 31;
    const int mbase = w * 16;
    const int nbase = lane * 4;

    const int ar = tid >> 1;
    const int ac = (tid & 1) * 8;
    const int bk = tid >> 5;
    const int bn = (tid & 31) << 2;

    float4 pa0 = *(const float4*)(A + (long)ar * lda + ac);
    float4 pa1 = *(const float4*)(A + (long)ar * lda + ac + 4);
    float4 pb  = *(const float4*)(B + (long)bk * ldb + bn);
    {
        float* As0 = sm;
        STORE_A_STAGE(As0);
        float* Bs0 = sm + 2 * A_BUF;
        *(float4*)&Bs0[bk * 128 + bn] = pb;
    }
    __syncthreads();

    ull acc[8][4];
    #pragma unroll
    for (int mp = 0; mp < 8; mp++)
        #pragma unroll
        for (int n = 0; n < 4; n++) acc[mp][n] = 0ull;

    for (int s = 0; s < nk; s++) {
        const int buf = s & 1;
        if (s + 1 < nk) {
            const float* A1 = A + (s + 1) * BKC;
            const float* B1 = B + (long)((s + 1) * BKC) * ldb;
            pa0 = *(const float4*)(A1 + (long)ar * lda + ac);
            pa1 = *(const float4*)(A1 + (long)ar * lda + ac + 4);
            pb  = *(const float4*)(B1 + (long)bk * ldb + bn);
        }
        const float* sa = sm + buf * A_BUF;
        const float* sb = sm + 2 * A_BUF + buf * B_BUF;
        FMA_BLOCK(sa, sb)
        if (s + 1 < nk) {
            __syncthreads();
            float* Asn = sm + (buf ^ 1) * A_BUF;
            float* Bsn = sm + 2 * A_BUF + (buf ^ 1) * B_BUF;
            STORE_A_STAGE(Asn);
            *(float4*)&Bsn[bk * 128 + bn] = pb;
            __syncthreads();
        }
    }

    #pragma unroll
    for (int mp = 0; mp < 8; mp++) {
        float2 u0 = unpk2(acc[mp][0]);
        float2 u1 = unpk2(acc[mp][1]);
        float2 u2 = unpk2(acc[mp][2]);
        float2 u3 = unpk2(acc[mp][3]);
        const int r0 = rowT * 256 + mbase + 2 * mp;
        float* cp = C + (long)r0 * ldc + colT * 128 + nbase;
        *(float4*)cp         = make_float4(u0.x, u1.x, u2.x, u3.x);
        *(float4*)(cp + ldc) = make_float4(u0.y, u1.y, u2.y, u3.y);
    }
}

// ============ qk_gemm: K=256 compile-time (16 chunks fully unrolled) ========
// A = Q (b,h,s,d): 2048x256 per z ; B = Kt (b): 256x2048 ; C = logits
// causal: skip tiles with colT*128 > rowT*256+255
__global__ __launch_bounds__(512)
void qk_gemm(const float* __restrict__ A, const float* __restrict__ B,
             float* __restrict__ C)
{
    extern __shared__ float sm[];
    const int tid = threadIdx.x;
    const int z = blockIdx.z, b = z >> 3;
    const int rowT = blockIdx.y, colT = blockIdx.x;
    if (colT * 128 > rowT * 256 + 255) return;

    A += (long)z * ((long)SEQ * HD) + (long)(rowT * 256) * HD;
    B += (long)b * ((long)HD * SEQ) + colT * 128;
    C += (long)b * ((long)NH * SEQ * SEQ) + (long)(z & 7) * SEQ * SEQ;

    const int w    = tid >> 5;
    const int lane = tid & 31;
    const int mbase = w * 16;
    const int nbase = lane * 4;

    const int ar = tid >> 1;
    const int ac = (tid & 1) * 8;
    const int bk = tid >> 5;
    const int bn = (tid & 31) << 2;

    float4 pa0 = *(const float4*)(A + (long)ar * HD + ac);
    float4 pa1 = *(const float4*)(A + (long)ar * HD + ac + 4);
    float4 pb  = *(const float4*)(B + (long)bk * SEQ + bn);
    {
        float* As0 = sm;
        STORE_A_STAGE(As0);
        float* Bs0 = sm + 2 * A_BUF;
        *(float4*)&Bs0[bk * 128 + bn] = pb;
    }
    __syncthreads();

    ull acc[8][4];
    #pragma unroll
    for (int mp = 0; mp < 8; mp++)
        #pragma unroll
        for (int n = 0; n < 4; n++) acc[mp][n] = 0ull;

    #pragma unroll
    for (int s = 0; s < 16; s++) {
        const int buf = s & 1;
        if (s < 15) {
            const float* A1 = A + (s + 1) * BKC;
            const float* B1 = B + (long)((s + 1) * BKC) * SEQ;
            pa0 = *(const float4*)(A1 + (long)ar * HD + ac);
            pa1 = *(const float4*)(A1 + (long)ar * HD + ac + 4);
            pb  = *(const float4*)(B1 + (long)bk * SEQ + bn);
        }
        const float* sa = sm + buf * A_BUF;
        const float* sb = sm + 2 * A_BUF + buf * B_BUF;
        FMA_BLOCK(sa, sb)
        if (s < 15) {
            __syncthreads();
            float* Asn = sm + (buf ^ 1) * A_BUF;
            float* Bsn = sm + 2 * A_BUF + (buf ^ 1) * B_BUF;
            STORE_A_STAGE(Asn);
            *(float4*)&Bsn[bk * 128 + bn] = pb;
            __syncthreads();
        }
    }

    #pragma unroll
    for (int mp = 0; mp < 8; mp++) {
        float2 u0 = unpk2(acc[mp][0]);
        float2 u1 = unpk2(acc[mp][1]);
        float2 u2 = unpk2(acc[mp][2]);
        float2 u3 = unpk2(acc[mp][3]);
        const int r0 = rowT * 256 + mbase + 2 * mp;
        float* cp = C + (long)r0 * SEQ + colT * 128 + nbase;
        *(float4*)cp         = make_float4(u0.x, u1.x, u2.x, u3.x);
        *(float4*)(cp + SEQ) = make_float4(u0.y, u1.y, u2.y, u3.y);
    }
}

// ---------------- weight concat [Wk | Wv], float4 ----------------
__global__ void concat_wkv(const float* __restrict__ Wk, const float* __restrict__ Wv,
                           float* __restrict__ Wkv) {
    int idx = blockIdx.x * 256 + threadIdx.x;
    int k = idx >> 7, n4 = idx & 127;
    float4 v = (n4 < 64) ? *(const float4*)(Wk + (long)k * 256 + n4 * 4)
                         : *(const float4*)(Wv + (long)k * 256 + (n4 - 64) * 4);
    *(float4*)(Wkv + (long)idx * 4) = v;
}

// ---------------- RoPE Q, float4 ----------------
__global__ __launch_bounds__(256)
void rope_q(const float* __restrict__ Qp, const float* __restrict__ cosb,
            const float* __restrict__ sinb, float* __restrict__ Qt) {
    const int idx = blockIdx.x * 256 + threadIdx.x;
    const int d4 = idx & 63;
    int t = idx >> 6;
    const int h = t & 7; t >>= 3;
    const int s = t & 2047;
    const int b = t >> 11;
    const long bs = (long)(b * SEQ + s);

    const float* src = Qp + bs * 2048 + h * 256;
    float4 x  = *(const float4*)(src + d4 * 4);
    float4 xp = (d4 < 32) ? *(const float4*)(src + (d4 + 32) * 4)
                          : *(const float4*)(src + (d4 - 32) * 4);
    const float sgn = (d4 < 32) ? -1.0f : 1.0f;
    float4 c = *(const float4*)(cosb + bs * 256 + d4 * 4);
    float4 sn = *(const float4*)(sinb + bs * 256 + d4 * 4);

    float4 o;
    o.x = (x.x * c.x + sgn * xp.x * sn.x) * SCALING;
    o.y = (x.y * c.y + sgn * xp.y * sn.y) * SCALING;
    o.z = (x.z * c.z + sgn * xp.z * sn.z) * SCALING;
    o.w = (x.w * c.w + sgn * xp.w * sn.w) * SCALING;
    *(float4*)(Qt + ((long)(b * NH + h) * SEQ + s) * 256 + d4 * 4) = o;
}

// ---------------- RoPE K + transpose -> Kt (b, d, s2) ----------------
__global__ void rope_kT(const float* __restrict__ KV, const float* __restrict__ cosb,
                        const float* __restrict__ sinb, float* __restrict__ Kt) {
    __shared__ float t[32][33];
    const int b = blockIdx.z;
    const int d0 = blockIdx.y * 32;
    const int s0 = blockIdx.x * 32;
    const int tx = threadIdx.x, ty = threadIdx.y;

    const int d = d0 + tx;
    const int s2 = s0 + ty;
    const int dp = (d < 128) ? d + 128 : d - 128;
    const long tok = (long)(b * SEQ + s2);
    const float x  = KV[tok * 512 + d];
    const float xp = KV[tok * 512 + dp];
    const float rot = (d < 128) ? -xp : xp;
    const float c = cosb[tok * 256 + d];
    const float sv = sinb[tok * 256 + d];
    t[ty][tx] = x * c + rot * sv;
    __syncthreads();

    Kt[((long)(b * HD + d0 + ty)) * SEQ + s0 + tx] = t[tx][ty];
}

// ---------------- causal softmax ----------------
__global__ __launch_bounds__(256)
void softmax_causal(float* __restrict__ W) {
    const long row = blockIdx.x;
    const int r = (int)(row & 2047);
    const int len = r + 1;
    float* p = W + row * (long)SEQ;
    const int tid = threadIdx.x;
    __shared__ float red[256];

    float v[8];
    float m = -3.0e38f;
    #pragma unroll
    for (int j = 0; j < 8; j++) {
        const int c = tid + j * 256;
        v[j] = (c < len) ? p[c] : -3.0e38f;
        m = fmaxf(m, v[j]);
    }
    red[tid] = m; __syncthreads();
    for (int s = 128; s > 0; s >>= 1) {
        if (tid < s) red[tid] = fmaxf(red[tid], red[tid + s]);
        __syncthreads();
    }
    m = red[0]; __syncthreads();

    float sum = 0.0f;
    #pragma unroll
    for (int j = 0; j < 8; j++) {
        const int c = tid + j * 256;
        v[j] = (c < len) ? __expf(v[j] - m) : 0.0f;
        sum += v[j];
    }
    red[tid] = sum; __syncthreads();
    for (int s = 128; s > 0; s >>= 1) {
        if (tid < s) red[tid] += red[tid + s];
        __syncthreads();
    }
    const float inv = 1.0f / red[0]; __syncthreads();

    #pragma unroll
    for (int j = 0; j < 8; j++) {
        const int c = tid + j * 256;
        p[c] = v[j] * inv;
    }
}

// ---------------- launch ----------------
// Q-projection (sgemm4) at launch index 3 (profiled slot), as in R13.
extern "C" void kernel_launch(void* const* d_in, const int* in_sizes, int n_in,
                              void* d_out, int out_size)
{
    const float* hs   = (const float*)d_in[0];
    const float* cosb = (const float*)d_in[1];
    const float* sinb = (const float*)d_in[2];
    const float* Wq   = (const float*)d_in[4];
    const float* Wk   = (const float*)d_in[5];
    const float* Wv   = (const float*)d_in[6];
    const float* Wo   = (const float*)d_in[7];

    float* out_attn = (float*)d_out;                          // (B,S,H)
    float* out_w    = (float*)d_out + (long)BSZ * SEQ * HID;  // (B,NH,S,S)

    const long SS = (long)SEQ * SEQ;

    cudaFuncSetAttribute(sgemm4, cudaFuncAttributeMaxDynamicSharedMemorySize, SMEM_DYN);
    cudaFuncSetAttribute(qk_gemm, cudaFuncAttributeMaxDynamicSharedMemorySize, SMEM_DYN);

    // 0) concat K/V weights
    concat_wkv<<<(HID * 128) / 256, 256>>>(Wk, Wv, g_Wkv);

    // 1) KV projection
    sgemm4<<<dim3(4, 16, 1), 512, SMEM_DYN>>>(hs, g_Wkv, g_KV,
        HID, HID, 512, 512, 0, 0, 0, 0, 1, 0);

    // 2) RoPE K (+transpose)
    rope_kT<<<dim3(64, 8, 2), dim3(32, 32)>>>(g_KV, cosb, sinb, g_Kt);

    // 3) Q projection   <-- profiled slot
    sgemm4<<<dim3(16, 16, 1), 512, SMEM_DYN>>>(hs, Wq, g_Qp,
        HID, HID, HID, HID, 0, 0, 0, 0, 1, 0);

    // 4) RoPE Q (float4, +transpose+scale)
    rope_q<<<(BSZ * SEQ * NH * 64) / 256, 256>>>(g_Qp, cosb, sinb, g_Q);

    // 5) logits = Q K^T, fully-unrolled K=256 kernel, causal tile skip
    qk_gemm<<<dim3(16, 8, 16), 512, SMEM_DYN>>>(g_Q, g_Kt, out_w);

    // 6) causal softmax
    softmax_causal<<<32768, 256>>>(out_w);

    // 7) attn = P @ V, K truncated, heavy rows first
    sgemm4<<<dim3(2, 8, 16), 512, SMEM_DYN>>>(out_w, g_KV + 256, g_AO,
        SEQ, SEQ, 512, HID,
        SS, (long)SEQ * 512, (long)SEQ * HID, (long)HD, NH, 1);

    // 8) output projection
    sgemm4<<<dim3(16, 16, 1), 512, SMEM_DYN>>>(g_AO, Wo, out_attn,
        HID, HID, HID, HID, 0, 0, 0, 0, 1, 0);
}

// round 17
// speedup vs baseline: 1.0519x; 1.0519x over previous
#include <cuda_runtime.h>
#include <cuda_bf16.h>
#include <cstdint>

typedef unsigned long long ull;

// ---------------- problem constants ----------------
#define BSZ 2
#define SEQ 2048
#define HID 2048
#define HD  256
#define NH  8
#define SCALING 0.0625f

// ---------------- scratch (device globals) ----------------
__device__ float g_Qp [(long)BSZ*SEQ*NH*HD];
__device__ float g_Q  [(long)BSZ*NH*SEQ*HD];
__device__ float g_KV [(long)BSZ*SEQ*512];
__device__ float g_KVp[2L*BSZ*SEQ*512];        // K-split partials
__device__ float g_Kt [(long)BSZ*HD*SEQ];
__device__ float g_AO [(long)BSZ*SEQ*NH*HD];
__device__ float g_Wkv[(long)HID*512];

// ---------------- f32x2 helpers ----------------
__device__ __forceinline__ ull pk2(float x) {
    ull r; unsigned u = __float_as_uint(x);
    asm("mov.b64 %0, {%1, %1};" : "=l"(r) : "r"(u));
    return r;
}
__device__ __forceinline__ ull fma2(ull a, ull b, ull c) {
    ull d;
    asm("fma.rn.f32x2 %0, %1, %2, %3;" : "=l"(d) : "l"(a), "l"(b), "l"(c));
    return d;
}
__device__ __forceinline__ float2 unpk2(ull v) {
    unsigned lo, hi;
    asm("mov.b64 {%0, %1}, %2;" : "=r"(lo), "=r"(hi) : "l"(v));
    return make_float2(__uint_as_float(lo), __uint_as_float(hi));
}

// ---------------- fp32 GEMM: 256x128 tile, 512 threads, 16m x 4n (R13) ------
#define BKC 16
#define A_BUF 4096
#define B_BUF 2048
#define SMEM_DYN ((2*A_BUF + 2*B_BUF) * 4)   // 48 KB

__global__ __launch_bounds__(512)
void sgemm4(const float* __restrict__ A, const float* __restrict__ B,
            float* __restrict__ C,
            int K, int lda, int ldb, int ldc,
            long sAz, long sBb, long sCb, long sCh, int nh,
            int causalQK, int causalPV)
{
    extern __shared__ float sm[];
    const int tid = threadIdx.x;
    const int z = blockIdx.z, b = z / nh, h = z - b * nh;
    int rowT = blockIdx.y;
    if (causalPV) rowT = gridDim.y - 1 - rowT;
    const int colT = blockIdx.x;
    if (causalQK && colT * 128 > rowT * 256 + 255) return;

    A += (long)z * sAz + (long)(rowT * 256) * lda;
    B += (long)b * sBb + colT * 128;
    C += (long)b * sCb + (long)h * sCh;

    const int Keff = causalPV ? min(K, (rowT + 1) * 256) : K;
    const int nk = Keff >> 4;

    const int w    = tid >> 5;
    const int lane = tid & 31;
    const int mbase = w * 16;
    const int nbase = lane * 4;

    const int ar = tid >> 1;
    const int ac = (tid & 1) * 8;
    const int bk = tid >> 5;
    const int bn = (tid & 31) << 2;

    float4 pa0 = *(const float4*)(A + (long)ar * lda + ac);
    float4 pa1 = *(const float4*)(A + (long)ar * lda + ac + 4);
    float4 pb  = *(const float4*)(B + (long)bk * ldb + bn);
    {
        float* As0 = sm;
        As0[(ac + 0) * 256 + ar] = pa0.x; As0[(ac + 1) * 256 + ar] = pa0.y;
        As0[(ac + 2) * 256 + ar] = pa0.z; As0[(ac + 3) * 256 + ar] = pa0.w;
        As0[(ac + 4) * 256 + ar] = pa1.x; As0[(ac + 5) * 256 + ar] = pa1.y;
        As0[(ac + 6) * 256 + ar] = pa1.z; As0[(ac + 7) * 256 + ar] = pa1.w;
        float* Bs0 = sm + 2 * A_BUF;
        *(float4*)&Bs0[bk * 128 + bn] = pb;
    }
    __syncthreads();

    ull acc[8][4];
    #pragma unroll
    for (int mp = 0; mp < 8; mp++)
        #pragma unroll
        for (int n = 0; n < 4; n++) acc[mp][n] = 0ull;

    for (int s = 0; s < nk; s++) {
        const int buf = s & 1;
        if (s + 1 < nk) {
            const float* A1 = A + (s + 1) * BKC;
            const float* B1 = B + (long)((s + 1) * BKC) * ldb;
            pa0 = *(const float4*)(A1 + (long)ar * lda + ac);
            pa1 = *(const float4*)(A1 + (long)ar * lda + ac + 4);
            pb  = *(const float4*)(B1 + (long)bk * ldb + bn);
        }
        const float* sa = sm + buf * A_BUF;
        const float* sb = sm + 2 * A_BUF + buf * B_BUF;
        #pragma unroll
        for (int k = 0; k < BKC; k++) {
            ulonglong2 aa0 = *(const ulonglong2*)&sa[k * 256 + mbase];
            ulonglong2 aa1 = *(const ulonglong2*)&sa[k * 256 + mbase + 4];
            ulonglong2 aa2 = *(const ulonglong2*)&sa[k * 256 + mbase + 8];
            ulonglong2 aa3 = *(const ulonglong2*)&sa[k * 256 + mbase + 12];
            float4 bv = *(const float4*)&sb[k * 128 + nbase];
            const ull b0 = pk2(bv.x), b1 = pk2(bv.y), b2 = pk2(bv.z), b3 = pk2(bv.w);
            acc[0][0] = fma2(aa0.x, b0, acc[0][0]);
            acc[0][1] = fma2(aa0.x, b1, acc[0][1]);
            acc[0][2] = fma2(aa0.x, b2, acc[0][2]);
            acc[0][3] = fma2(aa0.x, b3, acc[0][3]);
            acc[1][0] = fma2(aa0.y, b0, acc[1][0]);
            acc[1][1] = fma2(aa0.y, b1, acc[1][1]);
            acc[1][2] = fma2(aa0.y, b2, acc[1][2]);
            acc[1][3] = fma2(aa0.y, b3, acc[1][3]);
            acc[2][0] = fma2(aa1.x, b0, acc[2][0]);
            acc[2][1] = fma2(aa1.x, b1, acc[2][1]);
            acc[2][2] = fma2(aa1.x, b2, acc[2][2]);
            acc[2][3] = fma2(aa1.x, b3, acc[2][3]);
            acc[3][0] = fma2(aa1.y, b0, acc[3][0]);
            acc[3][1] = fma2(aa1.y, b1, acc[3][1]);
            acc[3][2] = fma2(aa1.y, b2, acc[3][2]);
            acc[3][3] = fma2(aa1.y, b3, acc[3][3]);
            acc[4][0] = fma2(aa2.x, b0, acc[4][0]);
            acc[4][1] = fma2(aa2.x, b1, acc[4][1]);
            acc[4][2] = fma2(aa2.x, b2, acc[4][2]);
            acc[4][3] = fma2(aa2.x, b3, acc[4][3]);
            acc[5][0] = fma2(aa2.y, b0, acc[5][0]);
            acc[5][1] = fma2(aa2.y, b1, acc[5][1]);
            acc[5][2] = fma2(aa2.y, b2, acc[5][2]);
            acc[5][3] = fma2(aa2.y, b3, acc[5][3]);
            acc[6][0] = fma2(aa3.x, b0, acc[6][0]);
            acc[6][1] = fma2(aa3.x, b1, acc[6][1]);
            acc[6][2] = fma2(aa3.x, b2, acc[6][2]);
            acc[6][3] = fma2(aa3.x, b3, acc[6][3]);
            acc[7][0] = fma2(aa3.y, b0, acc[7][0]);
            acc[7][1] = fma2(aa3.y, b1, acc[7][1]);
            acc[7][2] = fma2(aa3.y, b2, acc[7][2]);
            acc[7][3] = fma2(aa3.y, b3, acc[7][3]);
        }
        if (s + 1 < nk) {
            __syncthreads();
            float* Asn = sm + (buf ^ 1) * A_BUF;
            float* Bsn = sm + 2 * A_BUF + (buf ^ 1) * B_BUF;
            Asn[(ac + 0) * 256 + ar] = pa0.x; Asn[(ac + 1) * 256 + ar] = pa0.y;
            Asn[(ac + 2) * 256 + ar] = pa0.z; Asn[(ac + 3) * 256 + ar] = pa0.w;
            Asn[(ac + 4) * 256 + ar] = pa1.x; Asn[(ac + 5) * 256 + ar] = pa1.y;
            Asn[(ac + 6) * 256 + ar] = pa1.z; Asn[(ac + 7) * 256 + ar] = pa1.w;
            *(float4*)&Bsn[bk * 128 + bn] = pb;
            __syncthreads();
        }
    }

    #pragma unroll
    for (int mp = 0; mp < 8; mp++) {
        float2 u0 = unpk2(acc[mp][0]);
        float2 u1 = unpk2(acc[mp][1]);
        float2 u2 = unpk2(acc[mp][2]);
        float2 u3 = unpk2(acc[mp][3]);
        const int r0 = rowT * 256 + mbase + 2 * mp;
        float* cp = C + (long)r0 * ldc + colT * 128 + nbase;
        *(float4*)cp         = make_float4(u0.x, u1.x, u2.x, u3.x);
        *(float4*)(cp + ldc) = make_float4(u0.y, u1.y, u2.y, u3.y);
    }
}

// ---------------- add K-split partials: g_KV = p0 + p1 (float4) -------------
__global__ void add_kv(const float* __restrict__ P, float* __restrict__ KV) {
    const long HALF = (long)BSZ * SEQ * 512;
    long i = ((long)blockIdx.x * 256 + threadIdx.x) * 4;
    float4 a = *(const float4*)(P + i);
    float4 b = *(const float4*)(P + HALF + i);
    float4 o = make_float4(a.x + b.x, a.y + b.y, a.z + b.z, a.w + b.w);
    *(float4*)(KV + i) = o;
}

// ---------------- weight concat [Wk | Wv], float4 ----------------
__global__ void concat_wkv(const float* __restrict__ Wk, const float* __restrict__ Wv,
                           float* __restrict__ Wkv) {
    int idx = blockIdx.x * 256 + threadIdx.x;
    int k = idx >> 7, n4 = idx & 127;
    float4 v = (n4 < 64) ? *(const float4*)(Wk + (long)k * 256 + n4 * 4)
                         : *(const float4*)(Wv + (long)k * 256 + (n4 - 64) * 4);
    *(float4*)(Wkv + (long)idx * 4) = v;
}

// ---------------- RoPE Q, float4 ----------------
__global__ __launch_bounds__(256)
void rope_q(const float* __restrict__ Qp, const float* __restrict__ cosb,
            const float* __restrict__ sinb, float* __restrict__ Qt) {
    const int idx = blockIdx.x * 256 + threadIdx.x;
    const int d4 = idx & 63;
    int t = idx >> 6;
    const int h = t & 7; t >>= 3;
    const int s = t & 2047;
    const int b = t >> 11;
    const long bs = (long)(b * SEQ + s);

    const float* src = Qp + bs * 2048 + h * 256;
    float4 x  = *(const float4*)(src + d4 * 4);
    float4 xp = (d4 < 32) ? *(const float4*)(src + (d4 + 32) * 4)
                          : *(const float4*)(src + (d4 - 32) * 4);
    const float sgn = (d4 < 32) ? -1.0f : 1.0f;
    float4 c = *(const float4*)(cosb + bs * 256 + d4 * 4);
    float4 sn = *(const float4*)(sinb + bs * 256 + d4 * 4);

    float4 o;
    o.x = (x.x * c.x + sgn * xp.x * sn.x) * SCALING;
    o.y = (x.y * c.y + sgn * xp.y * sn.y) * SCALING;
    o.z = (x.z * c.z + sgn * xp.z * sn.z) * SCALING;
    o.w = (x.w * c.w + sgn * xp.w * sn.w) * SCALING;
    *(float4*)(Qt + ((long)(b * NH + h) * SEQ + s) * 256 + d4 * 4) = o;
}

// ---------------- RoPE K + transpose -> Kt (b, d, s2) ----------------
__global__ void rope_kT(const float* __restrict__ KV, const float* __restrict__ cosb,
                        const float* __restrict__ sinb, float* __restrict__ Kt) {
    __shared__ float t[32][33];
    const int b = blockIdx.z;
    const int d0 = blockIdx.y * 32;
    const int s0 = blockIdx.x * 32;
    const int tx = threadIdx.x, ty = threadIdx.y;

    const int d = d0 + tx;
    const int s2 = s0 + ty;
    const int dp = (d < 128) ? d + 128 : d - 128;
    const long tok = (long)(b * SEQ + s2);
    const float x  = KV[tok * 512 + d];
    const float xp = KV[tok * 512 + dp];
    const float rot = (d < 128) ? -xp : xp;
    const float c = cosb[tok * 256 + d];
    const float sv = sinb[tok * 256 + d];
    t[ty][tx] = x * c + rot * sv;
    __syncthreads();

    Kt[((long)(b * HD + d0 + ty)) * SEQ + s0 + tx] = t[tx][ty];
}

// ---------------- causal softmax ----------------
__global__ __launch_bounds__(256)
void softmax_causal(float* __restrict__ W) {
    const long row = blockIdx.x;
    const int r = (int)(row & 2047);
    const int len = r + 1;
    float* p = W + row * (long)SEQ;
    const int tid = threadIdx.x;
    __shared__ float red[256];

    float v[8];
    float m = -3.0e38f;
    #pragma unroll
    for (int j = 0; j < 8; j++) {
        const int c = tid + j * 256;
        v[j] = (c < len) ? p[c] : -3.0e38f;
        m = fmaxf(m, v[j]);
    }
    red[tid] = m; __syncthreads();
    for (int s = 128; s > 0; s >>= 1) {
        if (tid < s) red[tid] = fmaxf(red[tid], red[tid + s]);
        __syncthreads();
    }
    m = red[0]; __syncthreads();

    float sum = 0.0f;
    #pragma unroll
    for (int j = 0; j < 8; j++) {
        const int c = tid + j * 256;
        v[j] = (c < len) ? __expf(v[j] - m) : 0.0f;
        sum += v[j];
    }
    red[tid] = sum; __syncthreads();
    for (int s = 128; s > 0; s >>= 1) {
        if (tid < s) red[tid] += red[tid + s];
        __syncthreads();
    }
    const float inv = 1.0f / red[0]; __syncthreads();

    #pragma unroll
    for (int j = 0; j < 8; j++) {
        const int c = tid + j * 256;
        p[c] = v[j] * inv;
    }
}

// ---------------- launch ----------------
// Q-projection at launch index 3 (profiled slot), as in R13.
extern "C" void kernel_launch(void* const* d_in, const int* in_sizes, int n_in,
                              void* d_out, int out_size)
{
    const float* hs   = (const float*)d_in[0];
    const float* cosb = (const float*)d_in[1];
    const float* sinb = (const float*)d_in[2];
    const float* Wq   = (const float*)d_in[4];
    const float* Wk   = (const float*)d_in[5];
    const float* Wv   = (const float*)d_in[6];
    const float* Wo   = (const float*)d_in[7];

    float* out_attn = (float*)d_out;                          // (B,S,H)
    float* out_w    = (float*)d_out + (long)BSZ * SEQ * HID;  // (B,NH,S,S)

    const long SS = (long)SEQ * SEQ;

    cudaFuncSetAttribute(sgemm4, cudaFuncAttributeMaxDynamicSharedMemorySize, SMEM_DYN);

    // 0) concat K/V weights
    concat_wkv<<<(HID * 128) / 256, 256>>>(Wk, Wv, g_Wkv);

    // 1) KV projection, K split into 2 halves (128 CTAs instead of 64)
    //    z selects K-half: A += z*1024 (K offset), B += z*1024*512 (rows),
    //    C += z * partial-buffer-size
    sgemm4<<<dim3(4, 16, 2), 512, SMEM_DYN>>>(hs, g_Wkv, g_KVp,
        1024, HID, 512, 512,
        1024 /*sAz: K offset*/, (long)1024 * 512 /*sBb*/,
        (long)BSZ * SEQ * 512 /*sCb*/, 0, 1, 0, 0);

    // 2) combine partials
    add_kv<<<(unsigned)(((long)BSZ * SEQ * 512 / 4) / 256), 256>>>(g_KVp, g_KV);

    // 3) Q projection   <-- profiled slot
    sgemm4<<<dim3(16, 16, 1), 512, SMEM_DYN>>>(hs, Wq, g_Qp,
        HID, HID, HID, HID, 0, 0, 0, 0, 1, 0, 0);

    // 4) RoPE K (+transpose)
    rope_kT<<<dim3(64, 8, 2), dim3(32, 32)>>>(g_KV, cosb, sinb, g_Kt);

    // 5) RoPE Q (float4, +transpose+scale)
    rope_q<<<(BSZ * SEQ * NH * 64) / 256, 256>>>(g_Qp, cosb, sinb, g_Q);

    // 6) logits = Q K^T, causal tile skip
    sgemm4<<<dim3(16, 8, 16), 512, SMEM_DYN>>>(g_Q, g_Kt, out_w,
        HD, HD, SEQ, SEQ,
        (long)SEQ * HD, (long)HD * SEQ, (long)NH * SS, SS, NH, 1, 0);

    // 7) causal softmax
    softmax_causal<<<32768, 256>>>(out_w);

    // 8) attn = P @ V, K truncated, heavy rows first
    sgemm4<<<dim3(2, 8, 16), 512, SMEM_DYN>>>(out_w, g_KV + 256, g_AO,
        SEQ, SEQ, 512, HID,
        SS, (long)SEQ * 512, (long)SEQ * HID, (long)HD, NH, 0, 1);

    // 9) output projection
    sgemm4<<<dim3(16, 16, 1), 512, SMEM_DYN>>>(g_AO, Wo, out_attn,
        HID, HID, HID, HID, 0, 0, 0, 0, 1, 0, 0);
}